// round 1
// baseline (speedup 1.0000x reference)
#include <cuda_runtime.h>
#include <cuda_fp16.h>
#include <math.h>

// Problem constants (setup_inputs: B=512, K=256)
#define KDIM 256
#define NITER 50

// Shared memory layout (bytes)
#define CS_BYTES   131072          // 65536 halves: C then M' (scaled exp), swizzled
#define FS_OFF     131072          // 256 floats: f = 0.5*scores row
#define GV_OFF     (FS_OFF + 1024) // 256 floats: row sums -> g
#define WS_OFF     (GV_OFF + 1024) // 16 floats warp partial sums
#define WT_OFF     (WS_OFF + 64)   // 16 floats warp partial traces
#define WM_OFF     (WT_OFF + 64)   // 16 floats warp partial mins
#define CN_OFF     (WM_OFF + 64)   // 4 floats consts: A, Bc, eps, Cc
#define SMEM_BYTES (CN_OFF + 64)

__device__ float g_scratch[1024];  // per-batch losses

__device__ __forceinline__ float ex2f(float x) {
    float y;
    asm("ex2.approx.ftz.f32 %0, %1;" : "=f"(y) : "f"(x));
    return y;
}

extern "C" __global__ void __launch_bounds__(512, 1)
cacis_main(const float* __restrict__ scores,
           const int*   __restrict__ targets,
           const float* __restrict__ C)
{
    extern __shared__ unsigned char smraw[];
    unsigned int* Cs   = (unsigned int*)smraw;               // [256][128] u32 words (half2), swizzled
    float*        fs   = (float*)(smraw + FS_OFF);
    float*        gv   = (float*)(smraw + GV_OFF);
    float*        wsum = (float*)(smraw + WS_OFF);
    float*        wtr  = (float*)(smraw + WT_OFF);
    float*        wmin = (float*)(smraw + WM_OFF);
    float*        cons = (float*)(smraw + CN_OFF);

    const int b    = blockIdx.x;
    const int t    = threadIdx.x;
    const int lane = t & 31;
    const int wid  = t >> 5;

    // ---- Phase 0: f = 0.5*scores[b], zero g ----
    if (t < KDIM) {
        fs[t] = 0.5f * scores[b * KDIM + t];
        gv[t] = 0.0f;
    }
    __syncthreads();

    // ---- Phase 1: stream C[b] from HBM -> fp16 smem (swizzled), reduce sum/trace/min(f_i+f_j+C) ----
    const float4* __restrict__ C4 = (const float4*)(C + (size_t)b * (KDIM * KDIM));
    const float4* __restrict__ fs4 = (const float4*)fs;
    float psum = 0.0f, ptr = 0.0f, pmin = 3.402823466e38f;

    #pragma unroll 4
    for (int ch = t; ch < 16384; ch += 512) {
        const int i  = ch >> 6;          // row
        const int c4 = ch & 63;          // float4 index within row
        float4 cc = C4[ch];
        float  fi = fs[i];
        float4 fj = fs4[c4];

        float n0 = fi + fj.x + cc.x;
        float n1 = fi + fj.y + cc.y;
        float n2 = fi + fj.z + cc.z;
        float n3 = fi + fj.w + cc.w;
        pmin = fminf(pmin, fminf(fminf(n0, n1), fminf(n2, n3)));
        psum += (cc.x + cc.y) + (cc.z + cc.w);

        const int d = i - (c4 << 2);
        if ((unsigned)d < 4u) {
            float dv = (d == 0) ? cc.x : (d == 1) ? cc.y : (d == 2) ? cc.z : cc.w;
            ptr += dv;
        }

        __half2 a01 = __floats2half2_rn(cc.x, cc.y);
        __half2 a23 = __floats2half2_rn(cc.z, cc.w);
        const int w0 = c4 * 2;
        const int sw = i & 31;
        unsigned int* rowp = Cs + i * 128;
        rowp[w0 ^ sw]       = *(unsigned int*)&a01;
        rowp[(w0 + 1) ^ sw] = *(unsigned int*)&a23;
    }

    // warp reduce
    #pragma unroll
    for (int o = 16; o; o >>= 1) {
        psum += __shfl_down_sync(0xffffffffu, psum, o);
        ptr  += __shfl_down_sync(0xffffffffu, ptr, o);
        pmin  = fminf(pmin, __shfl_down_sync(0xffffffffu, pmin, o));
    }
    if (lane == 0) { wsum[wid] = psum; wtr[wid] = ptr; wmin[wid] = pmin; }
    __syncthreads();

    if (t == 0) {
        float s = 0.0f, tr = 0.0f, mn = 3.402823466e38f;
        #pragma unroll
        for (int w = 0; w < 16; w++) { s += wsum[w]; tr += wtr[w]; mn = fminf(mn, wmin[w]); }
        float eps = fmaxf((s - tr) / (float)(KDIM * KDIM - KDIM), 1e-8f);
        float k = 1.4426950408889634f / eps;        // log2(e)/eps
        cons[0] = -k;                               // A:   arg = num*A + Bc
        cons[1] = mn * k + 14.0f;                   // Bc:  (mn-num)*k + 14  => M' = M * 2^14
        cons[2] = eps;
        cons[3] = mn + 14.0f * 0.6931471805599453f * eps;  // Cc: conj = Cc - eps*ln(alpha^T M' alpha)
    }
    __syncthreads();

    // ---- Phase 2: in-place M' = 2^((mn-num)*k + 14) (fp16), accumulate row sums ----
    {
        const float A  = cons[0];
        const float Bc = cons[1];
        const int   i2 = t & 255;
        const int   hh = t >> 8;          // half-row split across 512 threads
        const int   sw = i2 & 31;
        unsigned int* rowp = Cs + i2 * 128;
        const float fi = fs[i2];
        const float2* __restrict__ fs2 = (const float2*)fs;
        float rs = 0.0f;

        const int wbeg = hh * 64;
        #pragma unroll 8
        for (int ww = wbeg; ww < wbeg + 64; ww++) {
            const int pa = ww ^ sw;
            unsigned int cw = rowp[pa];
            __half2 hc = *(__half2*)&cw;
            float2 cf = __half22float2(hc);
            float2 fj2 = fs2[ww];
            float a0 = fmaf(cf.x, A, fmaf(fi + fj2.x, A, Bc));
            float a1 = fmaf(cf.y, A, fmaf(fi + fj2.y, A, Bc));
            float m0 = ex2f(a0);
            float m1 = ex2f(a1);
            rs += m0 + m1;
            __half2 mh = __floats2half2_rn(m0, m1);
            rowp[pa] = *(unsigned int*)&mh;
        }
        atomicAdd(&gv[i2], rs);   // exactly two adds per row: commutative, deterministic
    }
    __syncthreads();

    // ---- Phase 3: Frank-Wolfe, single warp, registers only ----
    if (wid == 0) {
        float gr[8], al[8];
        unsigned rowoff[8];
        #pragma unroll
        for (int m = 0; m < 8; m++) {
            gr[m] = gv[lane + 32 * m];          // = 256 * (M' alpha0); scale irrelevant (gamma0 = 1)
            al[m] = 0.00390625f;                // 1/256
            rowoff[m] = (unsigned)(lane + 32 * m) * 128u;
        }

        for (int it = 0; it < NITER; it++) {
            const float gamma = 2.0f / (float)(it + 2);
            const float omg   = 1.0f - gamma;

            // argmin over 256 g values (positive floats: bits order-preserve), first-index tie-break
            unsigned umin = 0xffffffffu;
            #pragma unroll
            for (int m = 0; m < 8; m++) umin = min(umin, __float_as_uint(gr[m]));
            const unsigned vmin = __reduce_min_sync(0xffffffffu, umin);
            unsigned cand = 0xffffffffu;
            #pragma unroll
            for (int m = 7; m >= 0; m--)
                if (__float_as_uint(gr[m]) == vmin) cand = (unsigned)(lane + 32 * m);
            const unsigned idx = __reduce_min_sync(0xffffffffu, cand);

            // g <- (1-g)*g + gamma * M'[:, idx]; alpha update
            const unsigned jw  = idx >> 1;
            const int      shf = (idx & 1u) << 4;
            const unsigned pw  = jw ^ (unsigned)lane;   // (idx>>1) ^ (row&31), row&31 == lane
            #pragma unroll
            for (int m = 0; m < 8; m++) {
                unsigned cw = Cs[rowoff[m] + pw];
                unsigned hb = (cw >> shf) & 0xffffu;
                float colv = __half2float(__ushort_as_half((unsigned short)hb));
                gr[m] = fmaf(gamma, colv, omg * gr[m]);
                al[m] = fmaf(al[m], omg, ((unsigned)(lane + 32 * m) == idx) ? gamma : 0.0f);
            }
        }

        // dot = alpha^T (M' alpha)
        float dot = 0.0f;
        #pragma unroll
        for (int m = 0; m < 8; m++) dot = fmaf(al[m], gr[m], dot);
        #pragma unroll
        for (int o = 16; o; o >>= 1) dot += __shfl_xor_sync(0xffffffffu, dot, o);

        if (lane == 0) {
            const float eps = cons[2];
            const float Cc  = cons[3];
            float conj = Cc - eps * logf(dot);
            g_scratch[b] = conj - scores[b * KDIM + targets[b]];
        }
    }
}

extern "C" __global__ void cacis_reduce(float* __restrict__ out, int Btot)
{
    __shared__ float sbuf[256];
    const int t = threadIdx.x;
    float s = 0.0f;
    for (int i = t; i < Btot; i += 256) s += g_scratch[i];
    sbuf[t] = s;
    __syncthreads();
    #pragma unroll
    for (int o = 128; o; o >>= 1) {
        if (t < o) sbuf[t] += sbuf[t + o];
        __syncthreads();
    }
    if (t == 0) out[0] = sbuf[0] / (float)Btot;
}

extern "C" void kernel_launch(void* const* d_in, const int* in_sizes, int n_in,
                              void* d_out, int out_size)
{
    const float* scores  = (const float*)d_in[0];
    const int*   targets = (const int*)d_in[1];
    const float* C       = (const float*)d_in[2];
    const int Btot = in_sizes[1];

    cudaFuncSetAttribute(cacis_main, cudaFuncAttributeMaxDynamicSharedMemorySize, SMEM_BYTES);
    cacis_main<<<Btot, 512, SMEM_BYTES>>>(scores, targets, C);
    cacis_reduce<<<1, 256>>>((float*)d_out, Btot);
}

// round 4
// speedup vs baseline: 1.0142x; 1.0142x over previous
#include <cuda_runtime.h>
#include <cuda_fp16.h>

#define KDIM 256
#define NITER 50
#define NSTREAM 512
#define NTHREADS 544
#define BPC 4

// Shared memory layout (bytes)
#define CS_BYTES 131072                 // 256 rows x 64 uint2 units (fp16 M'), XOR-swizzled
#define FS_OFF   CS_BYTES               // 2 x 256 floats (double-buffered f = 0.5*scores)
#define GV_OFF   (FS_OFF + 2048)        // 256 floats row sums
#define WS_OFF   (GV_OFF + 1024)        // 16 warp partial sums
#define WT_OFF   (WS_OFF + 64)          // 16 warp partial traces
#define WM_OFF   (WT_OFF + 64)          // 16 warp partial mins
#define CN_OFF   (WM_OFF + 64)          // 4 consts: A, Bc, eps, Cc
#define GT_OFF   (CN_OFF + 32)          // 50 x float2 (gamma, 1-gamma)
#define FL_OFF   (GT_OFF + 8*NITER)     // last-CTA flag
#define RD_OFF   (FL_OFF + 32)          // 17 floats reduce scratch
#define SMEM_BYTES (RD_OFF + 128)

__device__ float g_scratch[1024];
__device__ unsigned int g_count = 0;

__device__ __forceinline__ float ex2f(float x) {
    float y;
    asm("ex2.approx.ftz.f32 %0, %1;" : "=f"(y) : "f"(x));
    return y;
}

// Phase A (streamers): HBM -> registers (fp16), partial sum/trace/min of (f_i+f_j+C)
__device__ __forceinline__ void load_batch(const float* __restrict__ Cb,
                                           const float* __restrict__ fsN,
                                           int t, unsigned (&cdat)[64],
                                           float* wsum, float* wtr, float* wmin)
{
    const int lane = t & 31, wid = t >> 5;
    const int c4 = t & 63, i0 = t >> 6;
    const float4* __restrict__ C4 = (const float4*)Cb;
    float4 fj = ((const float4*)fsN)[c4];
    float psum = 0.f, ptrc = 0.f, pmin = 3.402823466e38f;
    #pragma unroll
    for (int j = 0; j < 32; j++) {
        float4 cc = __ldcs(&C4[t + 512 * j]);
        int i = i0 + 8 * j;
        float fi = fsN[i];
        float m01 = fminf(fj.x + cc.x, fj.y + cc.y);
        float m23 = fminf(fj.z + cc.z, fj.w + cc.w);
        pmin = fminf(pmin, fi + fminf(m01, m23));
        psum += (cc.x + cc.y) + (cc.z + cc.w);
        int d = i - 4 * c4;
        if ((unsigned)d < 4u) {
            float dv = (d == 0) ? cc.x : (d == 1) ? cc.y : (d == 2) ? cc.z : cc.w;
            ptrc += dv;
        }
        __half2 h01 = __floats2half2_rn(cc.x, cc.y);
        __half2 h23 = __floats2half2_rn(cc.z, cc.w);
        cdat[2 * j]     = *(unsigned*)&h01;
        cdat[2 * j + 1] = *(unsigned*)&h23;
    }
    #pragma unroll
    for (int o = 16; o; o >>= 1) {
        psum += __shfl_down_sync(0xffffffffu, psum, o);
        ptrc += __shfl_down_sync(0xffffffffu, ptrc, o);
        pmin  = fminf(pmin, __shfl_down_sync(0xffffffffu, pmin, o));
    }
    if (lane == 0) { wsum[wid] = psum; wtr[wid] = ptrc; wmin[wid] = pmin; }
}

__device__ __forceinline__ void finalize_consts(float* cons, const float* wsum,
                                                const float* wtr, const float* wmin)
{
    float s = 0.f, tr = 0.f, mn = 3.402823466e38f;
    #pragma unroll
    for (int w = 0; w < 16; w++) { s += wsum[w]; tr += wtr[w]; mn = fminf(mn, wmin[w]); }
    float eps = fmaxf((s - tr) / 65280.0f, 1e-8f);          // K*K-K
    float k = 1.4426950408889634f / eps;                    // log2(e)/eps
    cons[0] = -k;                                           // A
    cons[1] = fmaf(mn, k, 14.0f);                           // Bc: M' = M * 2^14
    cons[2] = eps;
    cons[3] = fmaf(9.7040605278392342f, eps, mn);           // Cc = mn + 14*ln2*eps
}

// Phase B (streamers): registers -> fp16 M' in smem (swizzled 64-bit units) + row sums
__device__ __forceinline__ void transform_batch(uint2* Cs, const float* __restrict__ fsC,
                                                int t, const unsigned (&cdat)[64],
                                                float* gv, const float* cons)
{
    const int lane = t & 31;
    const int c4 = t & 63, i0 = t >> 6;
    const float A = cons[0], Bc = cons[1];
    float4 fj = ((const float4*)fsC)[c4];
    float bx = fmaf(fj.x, A, Bc);
    float by = fmaf(fj.y, A, Bc);
    float bz = fmaf(fj.z, A, Bc);
    float bw = fmaf(fj.w, A, Bc);
    #pragma unroll
    for (int j = 0; j < 32; j++) {
        int i = i0 + 8 * j;
        float fiA = fsC[i] * A;
        __half2 h01 = *(const __half2*)&cdat[2 * j];
        __half2 h23 = *(const __half2*)&cdat[2 * j + 1];
        float2 c01 = __half22float2(h01);
        float2 c23 = __half22float2(h23);
        float m0 = ex2f(fmaf(c01.x, A, fiA + bx));
        float m1 = ex2f(fmaf(c01.y, A, fiA + by));
        float m2 = ex2f(fmaf(c23.x, A, fiA + bz));
        float m3 = ex2f(fmaf(c23.y, A, fiA + bw));
        float cs = (m0 + m1) + (m2 + m3);
        __half2 o01 = __floats2half2_rn(m0, m1);
        __half2 o23 = __floats2half2_rn(m2, m3);
        uint2 st;
        st.x = *(unsigned*)&o01;
        st.y = *(unsigned*)&o23;
        Cs[i * 64 + (c4 ^ (i & 31))] = st;                  // conflict-free STS.64
        #pragma unroll
        for (int o = 16; o; o >>= 1) cs += __shfl_down_sync(0xffffffffu, cs, o);
        if (lane == 0) atomicAdd(&gv[i], cs);               // exactly 2 adds/row: deterministic
    }
}

// Frank-Wolfe: single warp, packed-key argmin (1 REDUX/iter), conflict-free LDS.64 column gather
__device__ __forceinline__ void run_fw(const uint2* __restrict__ Cs, const float* __restrict__ gv,
                                       const float* __restrict__ cons, const float2* __restrict__ gtab,
                                       const float* __restrict__ scores, const int* __restrict__ targets,
                                       int b, int lane)
{
    float gr[8], al[8];
    #pragma unroll
    for (int m = 0; m < 8; m++) { gr[m] = gv[lane + 32 * m]; al[m] = 0.00390625f; }
    for (int it = 0; it < NITER; it++) {
        float2 gg = gtab[it];
        unsigned key = 0xffffffffu;
        #pragma unroll
        for (int m = 0; m < 8; m++)
            key = min(key, (__float_as_uint(gr[m]) & 0xffffff00u) | (unsigned)(lane + 32 * m));
        unsigned kmin = __reduce_min_sync(0xffffffffu, key);
        unsigned idx = kmin & 0xffu;
        unsigned c4i = idx >> 2, sel = idx & 3u;
        const float gamma = gg.x, omg = gg.y;
        #pragma unroll
        for (int m = 0; m < 8; m++) {
            unsigned row = (unsigned)lane + 32u * m;
            uint2 u = Cs[row * 64u + (c4i ^ (unsigned)lane)];
            unsigned w  = (sel & 2u) ? u.y : u.x;
            unsigned hb = (sel & 1u) ? (w >> 16) : (w & 0xffffu);
            float colv = __half2float(__ushort_as_half((unsigned short)hb));
            gr[m] = fmaf(gamma, colv, omg * gr[m]);
            al[m] = fmaf(omg, al[m], (row == idx) ? gamma : 0.0f);
        }
    }
    float dot = 0.f;
    #pragma unroll
    for (int m = 0; m < 8; m++) dot = fmaf(al[m], gr[m], dot);
    #pragma unroll
    for (int o = 16; o; o >>= 1) dot += __shfl_xor_sync(0xffffffffu, dot, o);
    if (lane == 0) {
        float conj = cons[3] - cons[2] * __logf(dot);
        g_scratch[b] = conj - scores[b * KDIM + targets[b]];
    }
}

extern "C" __global__ void __launch_bounds__(NTHREADS, 1)
cacis_fused(const float* __restrict__ scores, const int* __restrict__ targets,
            const float* __restrict__ C, float* __restrict__ out, int B)
{
    extern __shared__ unsigned char smraw[];
    uint2*  Cs   = (uint2*)smraw;
    float*  fsb  = (float*)(smraw + FS_OFF);
    float*  gv   = (float*)(smraw + GV_OFF);
    float*  wsum = (float*)(smraw + WS_OFF);
    float*  wtr  = (float*)(smraw + WT_OFF);
    float*  wmin = (float*)(smraw + WM_OFF);
    float*  cons = (float*)(smraw + CN_OFF);
    float2* gtab = (float2*)(smraw + GT_OFF);
    int*    flg  = (int*)(smraw + FL_OFF);
    float*  rbuf = (float*)(smraw + RD_OFF);

    const int t = threadIdx.x, lane = t & 31, wid = t >> 5;
    const int cb = blockIdx.x;
    const int b0 = cb * BPC;
    const int nb = min(BPC, B - b0);

    unsigned cdat[64];

    // ---- prologue: fs(b0), gamma table, load+transform b0 ----
    if (t < KDIM) fsb[t] = 0.5f * scores[b0 * KDIM + t];
    if (t < NITER) { float g = 2.0f / (float)(t + 2); gtab[t] = make_float2(g, 1.0f - g); }
    __syncthreads();

    if (t < NSTREAM) load_batch(C + (size_t)b0 * (KDIM * KDIM), fsb, t, cdat, wsum, wtr, wmin);
    __syncthreads();

    if (t == 0) finalize_consts(cons, wsum, wtr, wmin);
    if (t < KDIM) gv[t] = 0.0f;
    if (t >= 256 && t < 512 && nb > 1)
        fsb[256 + (t - 256)] = 0.5f * scores[(b0 + 1) * KDIM + (t - 256)];
    __syncthreads();

    if (t < NSTREAM) transform_batch(Cs, fsb, t, cdat, gv, cons);
    __syncthreads();

    // ---- pipelined main loop: FW(b_k) || load(b_{k+1}) ----
    for (int k = 0; k < nb; k++) {
        const int has_next = (k + 1 < nb);
        if (wid == 16) {
            run_fw(Cs, gv, cons, gtab, scores, targets, b0 + k, lane);
        } else if (has_next) {
            load_batch(C + (size_t)(b0 + k + 1) * (KDIM * KDIM), fsb + 256 * ((k + 1) & 1),
                       t, cdat, wsum, wtr, wmin);
        }
        __syncthreads();
        if (has_next) {
            if (t == 0) finalize_consts(cons, wsum, wtr, wmin);
            if (t < KDIM) gv[t] = 0.0f;
            if (t >= 256 && t < 512 && (k + 2 < nb))
                fsb[256 * (k & 1) + (t - 256)] = 0.5f * scores[(b0 + k + 2) * KDIM + (t - 256)];
            __syncthreads();
            if (t < NSTREAM) transform_batch(Cs, fsb + 256 * ((k + 1) & 1), t, cdat, gv, cons);
            __syncthreads();
        }
    }

    // ---- fused cross-CTA reduction: last CTA sums g_scratch in fixed order ----
    if (t == 0) {
        __threadfence();
        unsigned prev = atomicAdd(&g_count, 1u);
        *flg = (prev == gridDim.x - 1) ? 1 : 0;
    }
    __syncthreads();
    if (*flg) {
        if (t == 0) g_count = 0;                 // reset for next graph replay
        __threadfence();
        float s = 0.f;
        for (int i = t; i < B; i += NTHREADS) s += __ldcg(&g_scratch[i]);
        #pragma unroll
        for (int o = 16; o; o >>= 1) s += __shfl_down_sync(0xffffffffu, s, o);
        if (lane == 0) rbuf[wid] = s;
        __syncthreads();
        if (t == 0) {
            float tot = 0.f;
            #pragma unroll
            for (int w = 0; w < 17; w++) tot += rbuf[w];
            out[0] = tot / (float)B;
        }
    }
}

extern "C" void kernel_launch(void* const* d_in, const int* in_sizes, int n_in,
                              void* d_out, int out_size)
{
    const float* scores  = (const float*)d_in[0];
    const int*   targets = (const int*)d_in[1];
    const float* C       = (const float*)d_in[2];
    const int B = in_sizes[1];
    const int grid = (B + BPC - 1) / BPC;

    cudaFuncSetAttribute(cacis_fused, cudaFuncAttributeMaxDynamicSharedMemorySize, SMEM_BYTES);
    cacis_fused<<<grid, NTHREADS, SMEM_BYTES>>>(scores, targets, C, (float*)d_out, B);
}

// round 5
// speedup vs baseline: 1.7858x; 1.7609x over previous
#include <cuda_runtime.h>
#include <cuda_fp16.h>

#define KDIM 256
#define NITER 50
#define NTH 512
#define BPC 4
#define NCHUNK 8
#define CHUNK_BYTES 32768        // 32 rows x 256 fp32
#define CHUNK_FLOATS 8192

// Shared memory layout (bytes)
#define CS_OFF   0               // 131072: 256 rows x 64 uint2 (fp16), XOR-swizzled
#define STG_OFF  131072          // 65536: 2 x 32KB fp32 staging chunks
#define FS_OFF   196608          // 1024: f = 0.5*scores
#define GV_OFF   197632          // 1024: row sums
#define WS_OFF   198656          // 64
#define WT_OFF   198720          // 64
#define WM_OFF   198784          // 64
#define CN_OFF   198848          // 32: A, Bc, eps, Cc
#define GT_OFF   198880          // 400: 50 x float2
#define MB_OFF   199296          // 16: two mbarriers
#define FL_OFF   199328          // 32
#define RD_OFF   199360          // 64
#define SMEM_BYTES 199424

__device__ float g_scratch[1024];
__device__ unsigned int g_count = 0;

__device__ __forceinline__ float ex2f(float x) {
    float y;
    asm("ex2.approx.ftz.f32 %0, %1;" : "=f"(y) : "f"(x));
    return y;
}

__device__ __forceinline__ void mbar_init(unsigned mbar, unsigned cnt) {
    asm volatile("mbarrier.init.shared::cta.b64 [%0], %1;" :: "r"(mbar), "r"(cnt) : "memory");
}
__device__ __forceinline__ void mbar_expect(unsigned mbar, unsigned bytes) {
    asm volatile("mbarrier.arrive.expect_tx.shared::cta.b64 _, [%0], %1;"
                 :: "r"(mbar), "r"(bytes) : "memory");
}
__device__ __forceinline__ void mbar_wait(unsigned mbar, unsigned phase) {
    asm volatile(
        "{\n\t"
        ".reg .pred P;\n\t"
        "LW_%=:\n\t"
        "mbarrier.try_wait.parity.shared::cta.b64 P, [%0], %1;\n\t"
        "@!P bra LW_%=;\n\t"
        "}\n"
        :: "r"(mbar), "r"(phase) : "memory");
}
__device__ __forceinline__ void tma_1d(unsigned dst, const void* src, unsigned bytes, unsigned mbar) {
    asm volatile(
        "cp.async.bulk.shared::cluster.global.mbarrier::complete_tx::bytes [%0], [%1], %2, [%3];"
        :: "r"(dst), "l"(src), "r"(bytes), "r"(mbar) : "memory");
}

__device__ __forceinline__ void finalize_consts(float* cons, const float* wsum,
                                                const float* wtr, const float* wmin)
{
    float s = 0.f, tr = 0.f, mn = 3.402823466e38f;
    #pragma unroll
    for (int w = 0; w < 16; w++) { s += wsum[w]; tr += wtr[w]; mn = fminf(mn, wmin[w]); }
    float eps = fmaxf((s - tr) / 65280.0f, 1e-8f);          // K*K-K
    float k = 1.4426950408889634f / eps;                    // log2(e)/eps
    cons[0] = -k;                                           // A
    cons[1] = fmaf(mn, k, 14.0f);                           // Bc: M' = M * 2^14
    cons[2] = eps;
    cons[3] = fmaf(9.7040605278392342f, eps, mn);           // Cc = mn + 14*ln2*eps
}

// Frank-Wolfe: single warp, packed-key argmin (1 REDUX/iter), conflict-free LDS.64 column gather
__device__ __forceinline__ void run_fw(const uint2* __restrict__ Cs, const float* __restrict__ gv,
                                       const float* __restrict__ cons, const float2* __restrict__ gtab,
                                       const float* __restrict__ scores, const int* __restrict__ targets,
                                       int b, int lane)
{
    float gr[8], al[8];
    #pragma unroll
    for (int m = 0; m < 8; m++) { gr[m] = gv[lane + 32 * m]; al[m] = 0.00390625f; }
    for (int it = 0; it < NITER; it++) {
        float2 gg = gtab[it];
        unsigned key = 0xffffffffu;
        #pragma unroll
        for (int m = 0; m < 8; m++)
            key = min(key, (__float_as_uint(gr[m]) & 0xffffff00u) | (unsigned)(lane + 32 * m));
        unsigned kmin = __reduce_min_sync(0xffffffffu, key);
        unsigned idx = kmin & 0xffu;
        unsigned c4i = idx >> 2, sel = idx & 3u;
        const float gamma = gg.x, omg = gg.y;
        #pragma unroll
        for (int m = 0; m < 8; m++) {
            unsigned row = (unsigned)lane + 32u * m;
            uint2 u = Cs[row * 64u + (c4i ^ (unsigned)lane)];
            unsigned w  = (sel & 2u) ? u.y : u.x;
            unsigned hb = (sel & 1u) ? (w >> 16) : (w & 0xffffu);
            float colv = __half2float(__ushort_as_half((unsigned short)hb));
            gr[m] = fmaf(gamma, colv, omg * gr[m]);
            al[m] = fmaf(omg, al[m], (row == idx) ? gamma : 0.0f);
        }
    }
    float dot = 0.f;
    #pragma unroll
    for (int m = 0; m < 8; m++) dot = fmaf(al[m], gr[m], dot);
    #pragma unroll
    for (int o = 16; o; o >>= 1) dot += __shfl_xor_sync(0xffffffffu, dot, o);
    if (lane == 0) {
        float conj = cons[3] - cons[2] * __logf(dot);
        g_scratch[b] = conj - scores[b * KDIM + targets[b]];
    }
}

extern "C" __global__ void __launch_bounds__(NTH, 1)
cacis_fused(const float* __restrict__ scores, const int* __restrict__ targets,
            const float* __restrict__ C, float* __restrict__ out, int B)
{
    extern __shared__ unsigned char smraw[];
    uint2*  Cs   = (uint2*)(smraw + CS_OFF);
    float*  fs   = (float*)(smraw + FS_OFF);
    float*  gv   = (float*)(smraw + GV_OFF);
    float*  wsum = (float*)(smraw + WS_OFF);
    float*  wtr  = (float*)(smraw + WT_OFF);
    float*  wmin = (float*)(smraw + WM_OFF);
    float*  cons = (float*)(smraw + CN_OFF);
    float2* gtab = (float2*)(smraw + GT_OFF);
    int*    flg  = (int*)(smraw + FL_OFF);
    float*  rbuf = (float*)(smraw + RD_OFF);
    const float4* fs4 = (const float4*)fs;

    const unsigned smem_base = (unsigned)__cvta_generic_to_shared(smraw);
    const unsigned stg_a[2] = { smem_base + STG_OFF, smem_base + STG_OFF + CHUNK_BYTES };
    const unsigned mb_a[2]  = { smem_base + MB_OFF, smem_base + MB_OFF + 8 };

    const int t = threadIdx.x, lane = t & 31, wid = t >> 5;
    const int b0 = blockIdx.x * BPC;
    const int nb = min(BPC, B - b0);

    // ---- prologue ----
    if (t == 0) { mbar_init(mb_a[0], 1); mbar_init(mb_a[1], 1); }
    if (t < KDIM) fs[t] = 0.5f * scores[b0 * KDIM + t];
    if (t < NITER) { float g = 2.0f / (float)(t + 2); gtab[t] = make_float2(g, 1.0f - g); }
    __syncthreads();

    if (t == 0) {
        const float* Cb0 = C + (size_t)b0 * (KDIM * KDIM);
        mbar_expect(mb_a[0], CHUNK_BYTES); tma_1d(stg_a[0], Cb0, CHUNK_BYTES, mb_a[0]);
        mbar_expect(mb_a[1], CHUNK_BYTES); tma_1d(stg_a[1], Cb0 + CHUNK_FLOATS, CHUNK_BYTES, mb_a[1]);
    }
    unsigned ph0 = 0, ph1 = 0;

    for (int k = 0; k < nb; k++) {
        const float* Cb = C + (size_t)(b0 + k) * (KDIM * KDIM);
        float psum = 0.f, ptrc = 0.f, pmin = 3.402823466e38f;

        // ---- convert loop: TMA chunks -> reductions + fp16 Cs (double-buffered) ----
        for (int c = 0; c < NCHUNK; c++) {
            const int bi = c & 1;
            if (bi == 0) { mbar_wait(mb_a[0], ph0); ph0 ^= 1; }
            else         { mbar_wait(mb_a[1], ph1); ph1 ^= 1; }
            const float4* stgp = (const float4*)(smraw + STG_OFF + bi * CHUNK_BYTES);
            #pragma unroll
            for (int kk = 0; kk < 4; kk++) {
                const int u = t + 512 * kk;
                const int rl = u >> 6, w = u & 63;
                const int r = c * 32 + rl;
                float4 cc = stgp[u];
                float fi = fs[r];
                float4 fj = fs4[w];
                float m01 = fminf(fj.x + cc.x, fj.y + cc.y);
                float m23 = fminf(fj.z + cc.z, fj.w + cc.w);
                pmin = fminf(pmin, fi + fminf(m01, m23));
                psum += (cc.x + cc.y) + (cc.z + cc.w);
                const int d = r - 4 * w;
                if ((unsigned)d < 4u)
                    ptrc += (d == 0) ? cc.x : (d == 1) ? cc.y : (d == 2) ? cc.z : cc.w;
                __half2 h01 = __floats2half2_rn(cc.x, cc.y);
                __half2 h23 = __floats2half2_rn(cc.z, cc.w);
                uint2 st;
                st.x = *(unsigned*)&h01;
                st.y = *(unsigned*)&h23;
                Cs[r * 64 + (w ^ (r & 31))] = st;
            }
            __syncthreads();                       // buffer bi fully consumed
            if (t == 0 && c + 2 < NCHUNK) {
                mbar_expect(mb_a[bi], CHUNK_BYTES);
                tma_1d(stg_a[bi], Cb + (c + 2) * CHUNK_FLOATS, CHUNK_BYTES, mb_a[bi]);
            }
        }

        // ---- reduce partials ----
        #pragma unroll
        for (int o = 16; o; o >>= 1) {
            psum += __shfl_down_sync(0xffffffffu, psum, o);
            ptrc += __shfl_down_sync(0xffffffffu, ptrc, o);
            pmin  = fminf(pmin, __shfl_down_sync(0xffffffffu, pmin, o));
        }
        if (lane == 0) { wsum[wid] = psum; wtr[wid] = ptrc; wmin[wid] = pmin; }
        __syncthreads();
        if (t == 0) finalize_consts(cons, wsum, wtr, wmin);
        if (t < KDIM) gv[t] = 0.0f;
        __syncthreads();

        // ---- prefetch chunks 0,1 of next batch (staging free; hides behind transform+FW) ----
        if (t == 0 && k + 1 < nb) {
            const float* Cn = C + (size_t)(b0 + k + 1) * (KDIM * KDIM);
            mbar_expect(mb_a[0], CHUNK_BYTES); tma_1d(stg_a[0], Cn, CHUNK_BYTES, mb_a[0]);
            mbar_expect(mb_a[1], CHUNK_BYTES); tma_1d(stg_a[1], Cn + CHUNK_FLOATS, CHUNK_BYTES, mb_a[1]);
        }

        // ---- transform: Cs fp16 C -> fp16 M' = 2^((mn-num)/eps*log2e + 14), row sums ----
        {
            const float A = cons[0], Bc = cons[1];
            const int i = t & 255, hh = t >> 8, sw = i & 31;
            uint2* rowp = Cs + i * 64;
            const float fiAB = fmaf(fs[i], A, Bc);
            float rs = 0.f;
            #pragma unroll 8
            for (int ww = hh * 32; ww < hh * 32 + 32; ww++) {
                const int pa = ww ^ sw;
                uint2 uu = rowp[pa];
                float2 c01 = __half22float2(*(__half2*)&uu.x);
                float2 c23 = __half22float2(*(__half2*)&uu.y);
                float4 fj = fs4[ww];
                float m0 = ex2f(fmaf(c01.x, A, fmaf(fj.x, A, fiAB)));
                float m1 = ex2f(fmaf(c01.y, A, fmaf(fj.y, A, fiAB)));
                float m2 = ex2f(fmaf(c23.x, A, fmaf(fj.z, A, fiAB)));
                float m3 = ex2f(fmaf(c23.y, A, fmaf(fj.w, A, fiAB)));
                rs += (m0 + m1) + (m2 + m3);
                __half2 o01 = __floats2half2_rn(m0, m1);
                __half2 o23 = __floats2half2_rn(m2, m3);
                uint2 st;
                st.x = *(unsigned*)&o01;
                st.y = *(unsigned*)&o23;
                rowp[pa] = st;
            }
            atomicAdd(&gv[i], rs);                 // exactly 2 commutative adds per row
        }
        __syncthreads();

        // ---- FW (warp 0) || fs prefetch for next batch (warps 8-15) ----
        if (wid == 0) {
            run_fw(Cs, gv, cons, gtab, scores, targets, b0 + k, lane);
        } else if (t >= 256 && k + 1 < nb) {
            fs[t - 256] = 0.5f * scores[(b0 + k + 1) * KDIM + (t - 256)];
        }
        __syncthreads();
    }

    // ---- fused cross-CTA reduction: last CTA sums g_scratch in fixed order ----
    if (t == 0) {
        __threadfence();
        unsigned prev = atomicAdd(&g_count, 1u);
        *flg = (prev == gridDim.x - 1) ? 1 : 0;
    }
    __syncthreads();
    if (*flg) {
        if (t == 0) g_count = 0;                   // reset for next graph replay
        __threadfence();
        float s = 0.f;
        for (int i = t; i < B; i += NTH) s += __ldcg(&g_scratch[i]);
        #pragma unroll
        for (int o = 16; o; o >>= 1) s += __shfl_down_sync(0xffffffffu, s, o);
        if (lane == 0) rbuf[wid] = s;
        __syncthreads();
        if (t == 0) {
            float tot = 0.f;
            #pragma unroll
            for (int w = 0; w < 16; w++) tot += rbuf[w];
            out[0] = tot / (float)B;
        }
    }
}

extern "C" void kernel_launch(void* const* d_in, const int* in_sizes, int n_in,
                              void* d_out, int out_size)
{
    const float* scores  = (const float*)d_in[0];
    const int*   targets = (const int*)d_in[1];
    const float* C       = (const float*)d_in[2];
    const int B = in_sizes[1];
    const int grid = (B + BPC - 1) / BPC;

    cudaFuncSetAttribute(cacis_fused, cudaFuncAttributeMaxDynamicSharedMemorySize, SMEM_BYTES);
    cacis_fused<<<grid, NTH, SMEM_BYTES>>>(scores, targets, C, (float*)d_out, B);
}